// round 13
// baseline (speedup 1.0000x reference)
#include <cuda_runtime.h>
#include <math.h>

// Problem shapes (fixed by the dataset)
constexpr int B   = 512;
constexpr int N   = 8192;
constexpr int H   = 200;
constexpr int W   = 200;
constexpr int ENV = H * W;          // 40000 floats = 160000 bytes
constexpr int THREADS = 1024;

// Per-block partial sums (no device-side allocation allowed -> __device__ global)
__device__ float g_partials[B];

__global__ __launch_bounds__(THREADS, 1)
void collision_main_kernel(const float* __restrict__ opState,
                           const float* __restrict__ envs)
{
    extern __shared__ float smem[];        // ENV floats env slab + 32 floats reduce scratch
    float* env_s = smem;
    float* red   = smem + ENV;

    const int b   = blockIdx.x;
    const int tid = threadIdx.x;

    // ---- Stage this batch's 200x200 ESDF slab into shared memory (coalesced float4) ----
    {
        const float4* src = reinterpret_cast<const float4*>(envs + (size_t)b * ENV);
        float4*       dst = reinterpret_cast<float4*>(env_s);
        #pragma unroll 4
        for (int i = tid; i < ENV / 4; i += THREADS)
            dst[i] = src[i];
    }
    __syncthreads();

    // ---- Process 8192 points for this batch (8 per thread), bilinear gather from smem ----
    const float2* pts = reinterpret_cast<const float2*>(opState + (size_t)b * N * 2);
    float acc = 0.0f;

    #pragma unroll 2
    for (int i = tid; i < N; i += THREADS) {
        float2 p = pts[i];

        bool oor = (p.x < -9.9f) || (p.x > 9.9f) || (p.y < -9.9f) || (p.y > 9.9f);

        float px = fminf(fmaxf(p.x, -9.9f), 9.9f);
        float py = fminf(fmaxf(p.y, -9.9f), 9.9f);

        // Match reference op order: pos_m = pos - 0.5*RES; idx = floor((pos_m + 10)/RES)
        float tx = ((px - 0.05f) + 10.0f) / 0.1f;
        float ty = ((py - 0.05f) + 10.0f) / 0.1f;
        int ix = (int)floorf(tx);
        int iy = (int)floorf(ty);
        // Mathematically already in [0,198]; clamp only for memory safety.
        ix = min(max(ix, 0), H - 2);
        iy = min(max(iy, 0), W - 2);

        float cx = ((float)ix + 0.5f) * 0.1f - 10.0f;
        float cy = ((float)iy + 0.5f) * 0.1f - 10.0f;
        float dx = (px - cx) / 0.1f;
        float dy = (py - cy) / 0.1f;

        const float* r0 = env_s + ix * W + iy;
        float v00 = r0[0];
        float v01 = r0[1];
        float v10 = r0[W];
        float v11 = r0[W + 1];

        float vx0 = (1.0f - dx) * v00 + dx * v10;
        float vx1 = (1.0f - dx) * v01 + dx * v11;
        float v   = (1.0f - dy) * vx0 + dy * vx1;

        float d    = oor ? -1.0f : v;
        float viod = 10.0f * (0.3f - d);
        viod = fmaxf(viod, 0.0f);
        acc = fmaf(viod, viod, acc);
    }

    // ---- Block reduction: warp shuffle -> smem -> warp shuffle ----
    #pragma unroll
    for (int o = 16; o > 0; o >>= 1)
        acc += __shfl_xor_sync(0xffffffffu, acc, o);

    const int warp = tid >> 5;
    const int lane = tid & 31;
    if (lane == 0) red[warp] = acc;
    __syncthreads();

    if (warp == 0) {
        float s = (lane < THREADS / 32) ? red[lane] : 0.0f;
        #pragma unroll
        for (int o = 16; o > 0; o >>= 1)
            s += __shfl_xor_sync(0xffffffffu, s, o);
        if (lane == 0) g_partials[b] = s;
    }
}

// Reduce the 512 per-batch partials in double precision and write the mean.
__global__ void collision_finalize_kernel(float* __restrict__ out)
{
    const int tid = threadIdx.x;   // launched with 512 threads
    double v = (double)g_partials[tid];

    #pragma unroll
    for (int o = 16; o > 0; o >>= 1)
        v += __shfl_xor_sync(0xffffffffu, v, o);

    __shared__ double red[16];
    const int warp = tid >> 5;
    const int lane = tid & 31;
    if (lane == 0) red[warp] = v;
    __syncthreads();

    if (warp == 0) {
        double s = (lane < 16) ? red[lane] : 0.0;
        #pragma unroll
        for (int o = 8; o > 0; o >>= 1)
            s += __shfl_xor_sync(0xffffffffu, s, o);
        if (lane == 0)
            out[0] = (float)(s / ((double)B * (double)N));
    }
}

extern "C" void kernel_launch(void* const* d_in, const int* in_sizes, int n_in,
                              void* d_out, int out_size)
{
    const float* opState = (const float*)d_in[0];   // (B, N, 2) float32
    const float* envs    = (const float*)d_in[1];   // (B, 1, H, W) float32
    float*       out     = (float*)d_out;           // scalar float32

    constexpr int SMEM_BYTES = ENV * sizeof(float) + 32 * sizeof(float); // 160128 B

    // Raise dynamic smem cap (idempotent; not a stream op, capture-safe).
    cudaFuncSetAttribute(collision_main_kernel,
                         cudaFuncAttributeMaxDynamicSharedMemorySize, SMEM_BYTES);

    collision_main_kernel<<<B, THREADS, SMEM_BYTES>>>(opState, envs);
    collision_finalize_kernel<<<1, B>>>(out);
}

// round 14
// speedup vs baseline: 1.0014x; 1.0014x over previous
#include <cuda_runtime.h>
#include <cuda_fp16.h>
#include <math.h>

// Problem shapes (fixed by the dataset)
constexpr int B   = 512;
constexpr int N   = 8192;
constexpr int H   = 200;
constexpr int W   = 200;
constexpr int ENV = H * W;            // 40000 cells
constexpr int THREADS = 512;
constexpr int PPT = N / THREADS;      // 16 points per thread

// Scratch for cross-block reduction (no device-side allocation allowed)
__device__ float        g_partials[B];
__device__ unsigned int g_count = 0;  // self-resetting via atomicInc wrap

__global__ __launch_bounds__(THREADS, 2)
void collision_fused_kernel(const float* __restrict__ opState,
                            const float* __restrict__ envs,
                            float* __restrict__ out)
{
    extern __shared__ __align__(16) unsigned char smem_raw[];
    __half* env_s = reinterpret_cast<__half*>(smem_raw);                   // 80000 B
    double* redd  = reinterpret_cast<double*>(smem_raw + ENV * sizeof(__half)); // 16 doubles
    float*  redf  = reinterpret_cast<float*>(redd);                        // aliased (phases are sync-separated)
    volatile int* last_flag = reinterpret_cast<volatile int*>(redd + 16);

    const int b    = blockIdx.x;
    const int tid  = threadIdx.x;
    const int warp = tid >> 5;
    const int lane = tid & 31;

    // ---- 1) Prefetch this thread's 16 points into registers (overlaps slab stream) ----
    const float2* pts = reinterpret_cast<const float2*>(opState + (size_t)b * N * 2);
    float2 p[PPT];
    #pragma unroll
    for (int j = 0; j < PPT; j++)
        p[j] = pts[tid + j * THREADS];

    // ---- 2) Stream slab HBM(fp32) -> smem(fp16), coalesced float4 reads ----
    {
        const float4* src = reinterpret_cast<const float4*>(envs + (size_t)b * ENV);
        __half2*      dst = reinterpret_cast<__half2*>(env_s);
        for (int i = tid; i < ENV / 4; i += THREADS) {
            float4 v = src[i];
            dst[2 * i]     = __floats2half2_rn(v.x, v.y);
            dst[2 * i + 1] = __floats2half2_rn(v.z, v.w);
        }
    }
    __syncthreads();

    // ---- 3) Bilinear gather + penalty for 16 points (all operands in regs/smem) ----
    float acc = 0.0f;
    #pragma unroll
    for (int j = 0; j < PPT; j++) {
        float pxr = p[j].x, pyr = p[j].y;
        bool oor = (pxr < -9.9f) || (pxr > 9.9f) || (pyr < -9.9f) || (pyr > 9.9f);

        float px = fminf(fmaxf(pxr, -9.9f), 9.9f);
        float py = fminf(fmaxf(pyr, -9.9f), 9.9f);

        // Reference op order: idx = floor(((pos - 0.05) + 10) / 0.1)
        float tx = ((px - 0.05f) + 10.0f) / 0.1f;
        float ty = ((py - 0.05f) + 10.0f) / 0.1f;
        int ix = (int)floorf(tx);
        int iy = (int)floorf(ty);
        ix = min(max(ix, 0), H - 2);   // mathematically already in range; memory safety only
        iy = min(max(iy, 0), W - 2);

        float cx = ((float)ix + 0.5f) * 0.1f - 10.0f;
        float cy = ((float)iy + 0.5f) * 0.1f - 10.0f;
        float dx = (px - cx) / 0.1f;
        float dy = (py - cy) / 0.1f;

        const __half* r0 = env_s + ix * W + iy;
        float v00 = __half2float(r0[0]);
        float v01 = __half2float(r0[1]);
        float v10 = __half2float(r0[W]);
        float v11 = __half2float(r0[W + 1]);

        float vx0 = (1.0f - dx) * v00 + dx * v10;
        float vx1 = (1.0f - dx) * v01 + dx * v11;
        float v   = (1.0f - dy) * vx0 + dy * vx1;

        float d    = oor ? -1.0f : v;
        float viod = fmaxf(10.0f * (0.3f - d), 0.0f);
        acc = fmaf(viod, viod, acc);
    }

    // ---- 4) Block reduction (fp32) ----
    #pragma unroll
    for (int o = 16; o > 0; o >>= 1)
        acc += __shfl_xor_sync(0xffffffffu, acc, o);
    if (lane == 0) redf[warp] = acc;
    __syncthreads();

    if (warp == 0) {
        float s = (lane < THREADS / 32) ? redf[lane] : 0.0f;
        #pragma unroll
        for (int o = 16; o > 0; o >>= 1)
            s += __shfl_xor_sync(0xffffffffu, s, o);
        if (lane == 0) g_partials[b] = s;
    }
    __syncthreads();   // redf reads done before last_flag/redd reuse

    // ---- 5) Last-block-finishes finalization (fence + atomicInc wrap, deterministic) ----
    if (tid == 0) {
        __threadfence();                                   // publish g_partials[b]
        unsigned int old = atomicInc(&g_count, B - 1);     // wraps to 0 on the B-th arrival
        *last_flag = (old == (unsigned int)(B - 1)) ? 1 : 0;
    }
    __syncthreads();

    if (*last_flag) {
        __threadfence();                   // acquire side: see all blocks' partials
        double v = (double)__ldcg(&g_partials[tid]);       // 512 threads, one partial each

        #pragma unroll
        for (int o = 16; o > 0; o >>= 1)
            v += __shfl_xor_sync(0xffffffffu, v, o);
        if (lane == 0) redd[warp] = v;
        __syncthreads();

        if (warp == 0) {
            double s = (lane < THREADS / 32) ? redd[lane] : 0.0;
            #pragma unroll
            for (int o = 8; o > 0; o >>= 1)
                s += __shfl_xor_sync(0xffffffffu, s, o);
            if (lane == 0)
                out[0] = (float)(s / ((double)B * (double)N));
        }
    }
}

extern "C" void kernel_launch(void* const* d_in, const int* in_sizes, int n_in,
                              void* d_out, int out_size)
{
    const float* opState = (const float*)d_in[0];   // (B, N, 2) float32
    const float* envs    = (const float*)d_in[1];   // (B, 1, H, W) float32
    float*       out     = (float*)d_out;           // scalar float32

    // 80000 B slab + 128 B reduce scratch + 16 B flag
    constexpr int SMEM_BYTES = ENV * sizeof(__half) + 16 * sizeof(double) + 16;

    cudaFuncSetAttribute(collision_fused_kernel,
                         cudaFuncAttributeMaxDynamicSharedMemorySize, SMEM_BYTES);

    collision_fused_kernel<<<B, THREADS, SMEM_BYTES>>>(opState, envs, out);
}